// round 12
// baseline (speedup 1.0000x reference)
#include <cuda_runtime.h>
#include <cstddef>
#include <cstdint>

#define V 49688
#define D 128
#define B 16
#define N 100

#define RPB 64                              // W rows staged per block
#define NBLOCKS ((V + RPB - 1) / RPB)       // 777
#define VD ((size_t)V * D)                  // floats per batch slice

__device__ __forceinline__ uint32_t smem_u32(const void* p) {
    uint32_t a;
    asm("{ .reg .u64 t; cvta.to.shared.u64 t, %1; cvt.u32.u64 %0, t; }"
        : "=r"(a) : "l"(p));
    return a;
}

// One block: stage rows [row0, row0+nrows) of W in SMEM, bulk-store the tile
// to all 16 batch slices via TMA (L1 bypassed), then patch gated rows.
// __launch_bounds__(256, 6): cap regs so 6 blocks/SM fit -> grid 777 runs in
// a single wave (6*148=888 slots) instead of 740+37 straggler wave.
__global__ __launch_bounds__(256, 6) void fused_tma_bcast_kernel(
    const int* __restrict__ nodes,    // (B, N)
    const float* __restrict__ x,      // (B*N, D), rows [0,N) used (node_feats)
    const float* __restrict__ W,      // (V, D)
    const float* __restrict__ alpha,  // (V, 1)
    float* __restrict__ out) {        // (B, V, D)

    __shared__ __align__(128) float tile[RPB * D];        // 32 KB
    __shared__ __align__(16) uint8_t tab[RPB][B];         // 1 KB

    const int tid = threadIdx.x;
    const int row0 = blockIdx.x * RPB;
    const int nrows = min(RPB, V - row0);

    // zero patch table: RPB*B/4 = 256 words, one per thread
    ((uint32_t*)tab)[tid] = 0u;
    __syncthreads();

    // scan the 1600 node entries for rows owned by this block
    for (int i = tid; i < B * N; i += 256) {
        int node = nodes[i];
        unsigned local = (unsigned)(node - row0);
        if (local < (unsigned)nrows) {
            tab[local][i / N] = (uint8_t)((i % N) + 1);
        }
    }

    // stage W tile into SMEM (coalesced float4)
    const float4* wsrc = (const float4*)(W + (size_t)row0 * D);
    float4* tdst = (float4*)tile;
    const int n4 = nrows * (D / 4);          // up to 2048 float4s
    for (int j = tid; j < n4; j += 256) {
        tdst[j] = wsrc[j];
    }

    // make generic-proxy SMEM writes visible to the async proxy, then sync
    asm volatile("fence.proxy.async.shared::cta;" ::: "memory");
    __syncthreads();

    // one thread issues 16 bulk stores SMEM -> each batch slice (bypasses L1)
    if (tid == 0) {
        uint32_t saddr = smem_u32(tile);
        uint32_t bytes = (uint32_t)(nrows * D * sizeof(float));
#pragma unroll
        for (int b = 0; b < B; ++b) {
            const float* dst = out + (size_t)b * VD + (size_t)row0 * D;
            asm volatile(
                "cp.async.bulk.global.shared::cta.bulk_group [%0], [%1], %2;"
                :: "l"(dst), "r"(saddr), "r"(bytes) : "memory");
        }
        asm volatile("cp.async.bulk.commit_group;" ::: "memory");
        asm volatile("cp.async.bulk.wait_group 0;" ::: "memory");
    }
    __syncthreads();   // bulk stores globally visible before patches

    // patch gated rows: out[b, v, :] = (1-a)*W[v,:] + a*x[pos,:]
    // 16 threads per row, 4 passes cover 64 rows.
    const int col = (tid & 15) * 8;          // float offset, 0..120
#pragma unroll
    for (int lrb = 0; lrb < RPB; lrb += 16) {
        int lr = lrb + (tid >> 4);
        if (lr >= nrows) continue;
        uint4 fl = *(const uint4*)tab[lr];
        if ((fl.x | fl.y | fl.z | fl.w) == 0u) continue;

        int v = row0 + lr;
        float a = alpha[v];
        float oma = 1.0f - a;
        const float4* wp = (const float4*)(tile + lr * D + col);
        float4 w0 = wp[0];
        float4 w1 = wp[1];
        const uint8_t* f = tab[lr];
#pragma unroll
        for (int b = 0; b < B; ++b) {
            uint8_t t = f[b];
            if (t == 0) continue;
            int pos = (int)t - 1;
            const float4* xp = (const float4*)(x + (size_t)pos * D + col);
            float4 x0 = xp[0];
            float4 x1 = xp[1];
            float4 r0, r1;
            r0.x = oma * w0.x + a * x0.x;  r0.y = oma * w0.y + a * x0.y;
            r0.z = oma * w0.z + a * x0.z;  r0.w = oma * w0.w + a * x0.w;
            r1.x = oma * w1.x + a * x1.x;  r1.y = oma * w1.y + a * x1.y;
            r1.z = oma * w1.z + a * x1.z;  r1.w = oma * w1.w + a * x1.w;
            float4* p = (float4*)(out + (size_t)b * VD + (size_t)v * D + col);
            p[0] = r0;
            p[1] = r1;
        }
    }
}

extern "C" void kernel_launch(void* const* d_in, const int* in_sizes, int n_in,
                              void* d_out, int out_size) {
    const int*   nodes = (const int*)d_in[0];    // (B, N) int32
    const float* x     = (const float*)d_in[1];  // (B*N, D) f32
    const float* W     = (const float*)d_in[2];  // (V, D) f32
    const float* alpha = (const float*)d_in[3];  // (V, 1) f32
    float* out = (float*)d_out;                  // (B, V, D) f32

    fused_tma_bcast_kernel<<<NBLOCKS, 256>>>(nodes, x, W, alpha, out);
}

// round 14
// speedup vs baseline: 1.1137x; 1.1137x over previous
#include <cuda_runtime.h>
#include <cstddef>
#include <cstdint>

#define V 49688
#define D 128
#define B 16
#define N 100

#define RPB 64                              // W rows staged per block
#define NBLOCKS ((V + RPB - 1) / RPB)       // 777
#define VD ((size_t)V * D)                  // floats per batch slice

__device__ __forceinline__ uint32_t smem_u32(const void* p) {
    uint32_t a;
    asm("{ .reg .u64 t; cvta.to.shared.u64 t, %1; cvt.u32.u64 %0, t; }"
        : "=r"(a) : "l"(p));
    return a;
}

// One block: stage rows [row0, row0+nrows) of W in SMEM, bulk-store the tile
// to all 16 batch slices via TMA (L1 bypassed), then patch gated rows.
// NOTE: no min-blocks occupancy cap — capping to 6/SM cut regs 46->40 and
// halved staging-load MLP, regressing 72.2 -> 82.1 us. Registers stay free.
__global__ __launch_bounds__(256) void fused_tma_bcast_kernel(
    const int* __restrict__ nodes,    // (B, N)
    const float* __restrict__ x,      // (B*N, D), rows [0,N) used (node_feats)
    const float* __restrict__ W,      // (V, D)
    const float* __restrict__ alpha,  // (V, 1)
    float* __restrict__ out) {        // (B, V, D)

    __shared__ __align__(128) float tile[RPB * D];        // 32 KB
    __shared__ __align__(16) uint8_t tab[RPB][B];         // 1 KB

    const int tid = threadIdx.x;
    const int row0 = blockIdx.x * RPB;
    const int nrows = min(RPB, V - row0);

    // zero patch table: RPB*B/4 = 256 words, one per thread
    ((uint32_t*)tab)[tid] = 0u;
    __syncthreads();

    // scan the 1600 node entries for rows owned by this block
    for (int i = tid; i < B * N; i += 256) {
        int node = nodes[i];
        unsigned local = (unsigned)(node - row0);
        if (local < (unsigned)nrows) {
            tab[local][i / N] = (uint8_t)((i % N) + 1);
        }
    }

    // stage W tile into SMEM (coalesced float4, 8 independent LDGs in flight)
    const float4* wsrc = (const float4*)(W + (size_t)row0 * D);
    float4* tdst = (float4*)tile;
    const int n4 = nrows * (D / 4);          // up to 2048 float4s
#pragma unroll 8
    for (int j = tid; j < n4; j += 256) {
        tdst[j] = wsrc[j];
    }

    // make generic-proxy SMEM writes visible to the async proxy, then sync
    asm volatile("fence.proxy.async.shared::cta;" ::: "memory");
    __syncthreads();

    // one thread issues 16 bulk stores SMEM -> each batch slice (bypasses L1)
    if (tid == 0) {
        uint32_t saddr = smem_u32(tile);
        uint32_t bytes = (uint32_t)(nrows * D * sizeof(float));
#pragma unroll
        for (int b = 0; b < B; ++b) {
            const float* dst = out + (size_t)b * VD + (size_t)row0 * D;
            asm volatile(
                "cp.async.bulk.global.shared::cta.bulk_group [%0], [%1], %2;"
                :: "l"(dst), "r"(saddr), "r"(bytes) : "memory");
        }
        asm volatile("cp.async.bulk.commit_group;" ::: "memory");
        asm volatile("cp.async.bulk.wait_group 0;" ::: "memory");
    }
    __syncthreads();   // bulk stores globally visible before patches

    // patch gated rows: out[b, v, :] = (1-a)*W[v,:] + a*x[pos,:]
    // 16 threads per row, 4 passes cover 64 rows.
    const int col = (tid & 15) * 8;          // float offset, 0..120
#pragma unroll
    for (int lrb = 0; lrb < RPB; lrb += 16) {
        int lr = lrb + (tid >> 4);
        if (lr >= nrows) continue;
        uint4 fl = *(const uint4*)tab[lr];
        if ((fl.x | fl.y | fl.z | fl.w) == 0u) continue;

        int v = row0 + lr;
        float a = alpha[v];
        float oma = 1.0f - a;
        const float4* wp = (const float4*)(tile + lr * D + col);
        float4 w0 = wp[0];
        float4 w1 = wp[1];
        const uint8_t* f = tab[lr];
#pragma unroll
        for (int b = 0; b < B; ++b) {
            uint8_t t = f[b];
            if (t == 0) continue;
            int pos = (int)t - 1;
            const float4* xp = (const float4*)(x + (size_t)pos * D + col);
            float4 x0 = xp[0];
            float4 x1 = xp[1];
            float4 r0, r1;
            r0.x = oma * w0.x + a * x0.x;  r0.y = oma * w0.y + a * x0.y;
            r0.z = oma * w0.z + a * x0.z;  r0.w = oma * w0.w + a * x0.w;
            r1.x = oma * w1.x + a * x1.x;  r1.y = oma * w1.y + a * x1.y;
            r1.z = oma * w1.z + a * x1.z;  r1.w = oma * w1.w + a * x1.w;
            float4* p = (float4*)(out + (size_t)b * VD + (size_t)v * D + col);
            p[0] = r0;
            p[1] = r1;
        }
    }
}

extern "C" void kernel_launch(void* const* d_in, const int* in_sizes, int n_in,
                              void* d_out, int out_size) {
    const int*   nodes = (const int*)d_in[0];    // (B, N) int32
    const float* x     = (const float*)d_in[1];  // (B*N, D) f32
    const float* W     = (const float*)d_in[2];  // (V, D) f32
    const float* alpha = (const float*)d_in[3];  // (V, 1) f32
    float* out = (float*)d_out;                  // (B, V, D) f32

    fused_tma_bcast_kernel<<<NBLOCKS, 256>>>(nodes, x, W, alpha, out);
}